// round 10
// baseline (speedup 1.0000x reference)
#include <cuda_runtime.h>
#include <cuda_bf16.h>
#include <cstdint>

// Problem constants
#define NB 2        // B
#define LL 16       // L
#define NN 10000    // N
#define FIN 8
#define HH 64       // H
#define PP 12       // P
#define EE 80000    // E
// Only l = 14,15 feed out[:, :, -1]. Slot s = b*2 + (l-14); row = [n][s][64].
#define SLOTS 4
#define ROWF (SLOTS * HH)   // 256 floats per node row
#define CAP 64              // per-node edge bucket capacity (max deg ~35)

#define KW 17                       // warps per block
#define KT (KW * 32)                // 544 threads
#define KG 148                      // grid = #SMs, 1 block/SM, all resident
#define TOTW (KG * KW)              // 2516 persistent warps

// Scratch
__device__ __align__(16) float g_h[(size_t)NN * ROWF];
__device__ __align__(16) float g_agg[(size_t)NN * ROWF];
__device__ int g_cnt[NN];                                // zero-init; cleaned per call
__device__ __align__(8) int2 g_edge[(size_t)NN * CAP];   // {col, val_bits}
__device__ unsigned g_bar;                               // barrier counter
__device__ unsigned g_done;                              // completion counter

// smem layout (one block = one SM)
#define SM_WT 0                                           // sWt4: 32*64 float4
#define SM_SU (SM_WT + 32 * 64 * 16)                      // 32768: su4 17*8*32 f4
#define SM_WO (SM_SU + KW * 8 * 32 * 16)                  // +69632 = 102400
#define SM_BT (SM_WO + PP * 64 * 4)                       // +3072  = 105472
#define SM_BO (SM_BT + 64 * 4)                            // +256   = 105728
#define SM_TOT (SM_BO + 64)                               //        = 105792
// proj weights alias the su4 region (only used in phase A)
#define SM_PW SM_SU                                       // 512 floats
#define SM_PB (SM_SU + 512 * 4)                           // 64 floats

__device__ __forceinline__ void grid_sync(unsigned target) {
    __threadfence();                 // make this thread's writes device-visible
    __syncthreads();
    if (threadIdx.x == 0) {
        atomicAdd(&g_bar, 1u);
        while (*(volatile unsigned*)&g_bar < target) { __nanosleep(64); }
    }
    __syncthreads();
    __threadfence();
}

__global__ void __launch_bounds__(KT, 1)
k_all(const float* __restrict__ x,
      const float* __restrict__ W_in,
      const float* __restrict__ b_in,
      const int* __restrict__ erow,
      const int* __restrict__ ecol,
      const float* __restrict__ evals,
      const float* __restrict__ W_tcn,
      const float* __restrict__ b_tcn,
      const float* __restrict__ W_out,
      const float* __restrict__ b_out,
      float* __restrict__ out) {
    extern __shared__ char dsm[];
    float4 (*sWt4)[64] = reinterpret_cast<float4(*)[64]>(dsm + SM_WT);
    float4 (*su4)[8][32] = reinterpret_cast<float4(*)[8][32]>(dsm + SM_SU);
    float*  sWtF = reinterpret_cast<float*>(dsm + SM_WT);
    float*  sWoT = reinterpret_cast<float*>(dsm + SM_WO);
    float*  sbt  = reinterpret_cast<float*>(dsm + SM_BT);
    float*  sbo  = reinterpret_cast<float*>(dsm + SM_BO);
    float*  sPW  = reinterpret_cast<float*>(dsm + SM_PW);
    float*  sPb  = reinterpret_cast<float*>(dsm + SM_PB);

    int tid = threadIdx.x;
    int w = tid >> 5, lane = tid & 31;
    int wg = blockIdx.x * KW + w;               // 0..2515 persistent warp id
    int gid = blockIdx.x * KT + tid;            // 0..80511

    // ====== weight staging for ALL phases (overlaps with binning/proj) ======
    // phase-C W_tcn: coalesced row reads, LDS-side transpose into sWt4
    for (int o = w; o < 64; o += KW) {
        const float* wr = W_tcn + o * 192;
        #pragma unroll
        for (int j = 0; j < 6; j++) {
            int f = lane + 32 * j;
            float val = __ldg(wr + f);
            int ip = f / 6;
            int c  = f - ip * 6;
            int comp = (c == 0) ? 0 : (c == 1) ? 1 : (c == 3) ? 2 : (c == 4) ? 3 : -1;
            if (comp >= 0) sWtF[ip * 256 + o * 4 + comp] = val;
        }
    }
    for (int t = tid; t < 64 * PP; t += KT) {
        float v = __ldg(W_out + t);
        int o = t / PP, p = t - o * PP;
        sWoT[p * 64 + o] = v;
    }
    if (tid < 64) sbt[tid] = b_tcn[tid];
    if (tid < PP) sbo[tid] = b_out[tid];
    // phase-A weights (aliased into su4 region, consumed before phase C)
    for (int i = tid; i < FIN * HH; i += KT) sPW[i] = W_in[i];
    if (tid >= 64 && tid < 128) sPb[tid - 64] = b_in[tid - 64];

    // ====== phase A: edge binning ======
    if (gid < EE) {
        int r = __ldg(erow + gid);
        int rank = atomicAdd(&g_cnt[r], 1);
        if (rank < CAP)
            g_edge[(size_t)r * CAP + rank] =
                make_int2(__ldg(ecol + gid), __float_as_int(__ldg(evals + gid)));
    }
    __syncthreads();

    // ====== phase A: input projection, rows (n,s) strided over 2516 warps ====
    for (int r = wg; r < NN * SLOTS; r += TOTW) {
        int n = r >> 2;
        int s = r & 3;
        int b = s >> 1;
        int l = 14 + (s & 1);
        const float4* xr = reinterpret_cast<const float4*>(
            x + (((size_t)b * LL + l) * NN + n) * FIN);
        float4 x0 = __ldg(xr);
        float4 x1 = __ldg(xr + 1);
        float xv[8] = {x0.x, x0.y, x0.z, x0.w, x1.x, x1.y, x1.z, x1.w};
        float* hrow = g_h + (size_t)r * HH;     // r == n*4+s
        #pragma unroll
        for (int rep = 0; rep < 2; rep++) {
            int hh = lane + rep * 32;
            float acc = sPb[hh];
            #pragma unroll
            for (int f = 0; f < 8; f++) acc = fmaf(xv[f], sPW[f * HH + hh], acc);
            hrow[hh] = fmaxf(acc, 0.0f);
        }
    }

    grid_sync(KG);                   // all h + edge buckets visible

    // ====== phase B: gather, half-rows strided over 2516 warps ======
    for (int hr = wg; hr < NN * 2; hr += TOTW) {
        int n    = hr >> 1;
        int half = hr & 1;
        int deg = g_cnt[n];
        if (deg > CAP) deg = CAP;
        const int2* ep = g_edge + (size_t)n * CAP;
        const float4* hbase = reinterpret_cast<const float4*>(g_h) + half * 32;

        float4 a = make_float4(0.f, 0.f, 0.f, 0.f);
        for (int k = 0; k < deg; k += 4) {
            int   c[4];
            float v[4];
            #pragma unroll
            for (int j = 0; j < 4; j++) {
                int kk = k + j < deg ? k + j : deg - 1;
                int2 e = __ldg(ep + kk);            // uniform, L1-hot
                c[j] = e.x;
                v[j] = (k + j < deg) ? __int_as_float(e.y) : 0.0f;
            }
            float4 h[4];
            #pragma unroll
            for (int j = 0; j < 4; j++)
                h[j] = __ldg(hbase + (size_t)c[j] * 64 + lane);
            #pragma unroll
            for (int j = 0; j < 4; j++) {
                a.x = fmaf(h[j].x, v[j], a.x);
                a.y = fmaf(h[j].y, v[j], a.y);
                a.z = fmaf(h[j].z, v[j], a.z);
                a.w = fmaf(h[j].w, v[j], a.w);
            }
        }
        float4* ap = reinterpret_cast<float4*>(g_agg) + (size_t)n * 64 + half * 32;
        ap[lane] = make_float4(fmaxf(a.x, 0.f), fmaxf(a.y, 0.f),
                               fmaxf(a.z, 0.f), fmaxf(a.w, 0.f));
    }

    grid_sync(2 * KG);               // all agg visible

    // ====== phase C: TCN-last + output projection (4 nodes per warp) ======
    if (gid < NN) g_cnt[gid] = 0;    // clean for next replay (read done in B)

    int nBase = wg * 4;              // 2516*4 = 10064 >= NN
    if (nBase < NN) {
        int tap = (lane >> 4) & 1;
        int hb8 = (lane & 15) * 8;
        #pragma unroll
        for (int m = 0; m < 4; m++) {
            int node = nBase + m;
            int nd = node < NN ? node : NN - 1;
            const float4* ar = reinterpret_cast<const float4*>(g_agg + (size_t)nd * ROWF);
            float4 r0 = __ldg(ar + lane);        // b = 0
            float4 r1 = __ldg(ar + lane + 32);   // b = 1
            float* d0 = reinterpret_cast<float*>(&su4[w][m * 2 + 0][0]);
            float* d1 = reinterpret_cast<float*>(&su4[w][m * 2 + 1][0]);
            d0[hb8 + 0 + tap] = r0.x;  d0[hb8 + 2 + tap] = r0.y;
            d0[hb8 + 4 + tap] = r0.z;  d0[hb8 + 6 + tap] = r0.w;
            d1[hb8 + 0 + tap] = r1.x;  d1[hb8 + 2 + tap] = r1.y;
            d1[hb8 + 4 + tap] = r1.z;  d1[hb8 + 6 + tap] = r1.w;
        }
        __syncwarp();

        float z0[8], z1[8];
        #pragma unroll
        for (int pp = 0; pp < 8; pp++) { z0[pp] = sbt[lane]; z1[pp] = sbt[lane + 32]; }
        #pragma unroll 4
        for (int ip = 0; ip < 32; ip++) {
            float4 wA = sWt4[ip][lane];
            float4 wB = sWt4[ip][lane + 32];
            #pragma unroll
            for (int pp = 0; pp < 8; pp++) {
                float4 u = su4[w][pp][ip];
                z0[pp] = fmaf(wA.x, u.x, fmaf(wA.y, u.y,
                         fmaf(wA.z, u.z, fmaf(wA.w, u.w, z0[pp]))));
                z1[pp] = fmaf(wB.x, u.x, fmaf(wB.y, u.y,
                         fmaf(wB.z, u.z, fmaf(wB.w, u.w, z1[pp]))));
            }
        }
        __syncwarp();
        #pragma unroll
        for (int pp = 0; pp < 8; pp++) {
            float* zf = reinterpret_cast<float*>(&su4[w][pp][0]);
            zf[lane]      = fmaxf(z0[pp], 0.0f);
            zf[lane + 32] = fmaxf(z1[pp], 0.0f);
        }
        __syncwarp();

        #pragma unroll
        for (int r = 0; r < 3; r++) {
            int q = lane + r * 32;               // 0..95
            int pp = q / PP;
            int p  = q - pp * PP;
            float y = sbo[p];
            const float4* z4 = &su4[w][pp][0];
            const float4* w4 = reinterpret_cast<const float4*>(sWoT + p * 64);
            #pragma unroll 4
            for (int oc = 0; oc < 16; oc++) {
                float4 zz = z4[oc];
                float4 ww = w4[oc];
                y = fmaf(zz.x, ww.x, fmaf(zz.y, ww.y,
                    fmaf(zz.z, ww.z, fmaf(zz.w, ww.w, y))));
            }
            int node = nBase + (pp >> 1);
            int b = pp & 1;
            if (node < NN)
                out[((size_t)b * PP + p) * NN + node] = y;
        }
    }

    // ====== barrier reset by the LAST finishing block (replay-safe) ======
    __syncthreads();
    if (tid == 0) {
        __threadfence();
        unsigned old = atomicAdd(&g_done, 1u);
        if (old == KG - 1) {                // everyone is past all spins
            g_done = 0u;
            *(volatile unsigned*)&g_bar = 0u;
            __threadfence();
        }
    }
}

// ---------------------------------------------------------------------------
extern "C" void kernel_launch(void* const* d_in, const int* in_sizes, int n_in,
                              void* d_out, int out_size) {
    const float* x     = (const float*)d_in[0];
    const int*   row   = (const int*)  d_in[1];
    const int*   col   = (const int*)  d_in[2];
    const float* vals  = (const float*)d_in[3];
    const float* W_in  = (const float*)d_in[4];
    const float* b_in  = (const float*)d_in[5];
    const float* W_tcn = (const float*)d_in[6];
    const float* b_tcn = (const float*)d_in[7];
    const float* W_out = (const float*)d_in[8];
    const float* b_out = (const float*)d_in[9];
    float* out = (float*)d_out;

    static bool attr_set = false;
    if (!attr_set) {
        cudaFuncSetAttribute(k_all,
                             cudaFuncAttributeMaxDynamicSharedMemorySize, SM_TOT);
        attr_set = true;
    }

    k_all<<<KG, KT, SM_TOT>>>(x, W_in, b_in, row, col, vals,
                              W_tcn, b_tcn, W_out, b_out, out);
}

// round 11
// speedup vs baseline: 1.1910x; 1.1910x over previous
#include <cuda_runtime.h>
#include <cuda_fp16.h>
#include <cstdint>

// Problem constants
#define NB 2        // B
#define LL 16       // L
#define NN 10000    // N
#define FIN 8
#define HH 64       // H
#define PP 12       // P
#define EE 80000    // E
// Only l = 14,15 feed out[:, :, -1]. Slot s = b*2 + (l-14); row = [n][s][64].
#define SLOTS 4
#define ROWF (SLOTS * HH)   // 256 values per node row
#define CAP 64              // per-node edge bucket capacity (max deg ~35)

// Scratch: h in fp16 (512B per node row), agg in fp32
__device__ __align__(16) __half g_h16[(size_t)NN * ROWF];
__device__ __align__(16) float g_agg[(size_t)NN * ROWF];
__device__ int g_cnt[NN];                                // zero-init; k_final cleans
__device__ __align__(8) int2 g_edge[(size_t)NN * CAP];   // {col, val_bits}

// ---------------------------------------------------------------------------
// K1: one warp per node: h[n,s,:] = relu(x[b,l,n,:]@W_in + b_in), s=0..3,
// stored as fp16 (lane computes h[2*lane], h[2*lane+1] -> one __half2 store);
// plus edge binning on the first EE threads.
// ---------------------------------------------------------------------------
__global__ void k_proj_bin(const float* __restrict__ x,
                           const float* __restrict__ W_in,
                           const float* __restrict__ b_in,
                           const int* __restrict__ erow,
                           const int* __restrict__ ecol,
                           const float* __restrict__ evals) {
    __shared__ float sW[FIN * HH];
    __shared__ float sb[HH];
    int tid = threadIdx.x;
    int gid = blockIdx.x * blockDim.x + tid;

    if (gid < EE) {
        int r = __ldg(erow + gid);
        int rank = atomicAdd(&g_cnt[r], 1);
        if (rank < CAP)
            g_edge[(size_t)r * CAP + rank] =
                make_int2(__ldg(ecol + gid), __float_as_int(__ldg(evals + gid)));
    }

    for (int i = tid; i < FIN * HH; i += blockDim.x) sW[i] = W_in[i];
    if (tid < HH) sb[tid] = b_in[tid];
    __syncthreads();

    int n = blockIdx.x * 8 + (tid >> 5);   // exactly 10000
    int lane = tid & 31;
    int hh0 = lane * 2;
    int hh1 = hh0 + 1;

    #pragma unroll
    for (int s = 0; s < SLOTS; s++) {
        int b = s >> 1;
        int l = 14 + (s & 1);
        const float4* xr = reinterpret_cast<const float4*>(
            x + (((size_t)b * LL + l) * NN + n) * FIN);
        float4 x0 = __ldg(xr);       // warp-broadcast 32B row
        float4 x1 = __ldg(xr + 1);
        float xv[8] = {x0.x, x0.y, x0.z, x0.w, x1.x, x1.y, x1.z, x1.w};

        float acc0 = sb[hh0];
        float acc1 = sb[hh1];
        #pragma unroll
        for (int f = 0; f < 8; f++) {
            acc0 = fmaf(xv[f], sW[f * HH + hh0], acc0);
            acc1 = fmaf(xv[f], sW[f * HH + hh1], acc1);
        }
        __half2* hrow = reinterpret_cast<__half2*>(
            g_h16 + ((size_t)n * SLOTS + s) * HH);
        hrow[lane] = __floats2half2_rn(fmaxf(acc0, 0.0f), fmaxf(acc1, 0.0f));
    }
}

// ---------------------------------------------------------------------------
// K2: gather — fp16 h: one warp per node row, ONE LDG.128 per edge covers
// the entire 512B row (lane holds 8 halves = values [8*lane .. 8*lane+7]).
// 4-edge unroll (MLP 4), uniform L1-hot edge-record loads, fp32 accumulate,
// relu'd fp32 agg out.
// ---------------------------------------------------------------------------
__global__ void k_gather() {
    int n = blockIdx.x * 8 + (threadIdx.x >> 5);   // exactly 10000 warps
    int lane = threadIdx.x & 31;

    int deg = g_cnt[n];
    if (deg > CAP) deg = CAP;
    const int2* ep = g_edge + (size_t)n * CAP;
    const float4* hb = reinterpret_cast<const float4*>(g_h16);  // 32 f4 / row

    float a[8];
    #pragma unroll
    for (int i = 0; i < 8; i++) a[i] = 0.0f;

    for (int k = 0; k < deg; k += 4) {
        int   c[4];
        float v[4];
        #pragma unroll
        for (int j = 0; j < 4; j++) {
            int kk = k + j < deg ? k + j : deg - 1;   // pad with last edge
            int2 e = __ldg(ep + kk);                  // uniform, L1-hot
            c[j] = e.x;
            v[j] = (k + j < deg) ? __int_as_float(e.y) : 0.0f;
        }
        float4 h4[4];
        #pragma unroll
        for (int j = 0; j < 4; j++)
            h4[j] = __ldg(hb + (size_t)c[j] * 32 + lane);
        #pragma unroll
        for (int j = 0; j < 4; j++) {
            const __half2* hp = reinterpret_cast<const __half2*>(&h4[j]);
            #pragma unroll
            for (int q = 0; q < 4; q++) {
                float2 f = __half22float2(hp[q]);
                a[q * 2 + 0] = fmaf(f.x, v[j], a[q * 2 + 0]);
                a[q * 2 + 1] = fmaf(f.y, v[j], a[q * 2 + 1]);
            }
        }
    }

    // write relu'd agg: lane owns floats [8*lane .. 8*lane+7] of the row
    float4* ap = reinterpret_cast<float4*>(g_agg + (size_t)n * ROWF + lane * 8);
    ap[0] = make_float4(fmaxf(a[0], 0.f), fmaxf(a[1], 0.f),
                        fmaxf(a[2], 0.f), fmaxf(a[3], 0.f));
    ap[1] = make_float4(fmaxf(a[4], 0.f), fmaxf(a[5], 0.f),
                        fmaxf(a[6], 0.f), fmaxf(a[7], 0.f));
}

// ---------------------------------------------------------------------------
// K3: final stage — persistent: grid 148, 17 warps, 4 nodes/warp (R8 proven).
// Also zeroes g_cnt for the next graph replay.
// ---------------------------------------------------------------------------
#define K3_WARPS 17
#define K3_THREADS (K3_WARPS * 32)            // 544
#define K3_NPW 4

#define SM3_WT 0
#define SM3_SU (SM3_WT + 32 * 64 * 16)                     // 32768
#define SM3_WO (SM3_SU + K3_WARPS * 8 * 32 * 16)           // +69632 = 102400
#define SM3_BT (SM3_WO + PP * 64 * 4)                      // +3072  = 105472
#define SM3_BO (SM3_BT + 64 * 4)                           // +256   = 105728
#define SM3_TOT (SM3_BO + 64)                              //        = 105792

__global__ void __launch_bounds__(K3_THREADS, 1)
k_final(const float* __restrict__ W_tcn,
        const float* __restrict__ b_tcn,
        const float* __restrict__ W_out,
        const float* __restrict__ b_out,
        float* __restrict__ out) {
    extern __shared__ char dsm[];
    float4 (*sWt4)[64] = reinterpret_cast<float4(*)[64]>(dsm + SM3_WT);
    float4 (*su4)[8][32] = reinterpret_cast<float4(*)[8][32]>(dsm + SM3_SU);
    float*  sWtF = reinterpret_cast<float*>(dsm + SM3_WT);   // float view
    float*  sWoT = reinterpret_cast<float*>(dsm + SM3_WO);
    float*  sbt  = reinterpret_cast<float*>(dsm + SM3_BT);
    float*  sbo  = reinterpret_cast<float*>(dsm + SM3_BO);

    int tid = threadIdx.x;
    int w = tid >> 5, lane = tid & 31;

    // zero g_cnt for next replay (148*544 = 80512 >= NN)
    {
        int t = blockIdx.x * K3_THREADS + tid;
        if (t < NN) g_cnt[t] = 0;
    }

    // ---- coalesced W_tcn staging: warp handles rows o = w, w+17, ... ----
    for (int o = w; o < 64; o += K3_WARPS) {
        const float* wr = W_tcn + o * 192;
        #pragma unroll
        for (int j = 0; j < 6; j++) {
            int f = lane + 32 * j;
            float val = __ldg(wr + f);         // fully coalesced
            int ip = f / 6;
            int c  = f - ip * 6;               // 0..5
            int comp = (c == 0) ? 0 : (c == 1) ? 1 : (c == 3) ? 2 : (c == 4) ? 3 : -1;
            if (comp >= 0)
                sWtF[ip * 256 + o * 4 + comp] = val;
        }
    }
    for (int t = tid; t < 64 * PP; t += K3_THREADS) {
        float v = __ldg(W_out + t);            // coalesced
        int o = t / PP, p = t - o * PP;
        sWoT[p * 64 + o] = v;
    }
    if (tid < 64) sbt[tid] = b_tcn[tid];
    if (tid < PP) sbo[tid] = b_out[tid];
    __syncthreads();

    int nBase = (blockIdx.x * K3_WARPS + w) * K3_NPW;
    if (nBase >= NN) return;

    // ---- load relu'd agg, scatter to interleaved su4 ----
    int tap = (lane >> 4) & 1;
    int hb8 = (lane & 15) * 8;
    #pragma unroll
    for (int m = 0; m < K3_NPW; m++) {
        int node = nBase + m;
        int nd = node < NN ? node : NN - 1;
        const float4* ar = reinterpret_cast<const float4*>(g_agg + (size_t)nd * ROWF);
        float4 r0 = __ldg(ar + lane);        // b = 0 data
        float4 r1 = __ldg(ar + lane + 32);   // b = 1 data
        float* d0 = reinterpret_cast<float*>(&su4[w][m * 2 + 0][0]);
        float* d1 = reinterpret_cast<float*>(&su4[w][m * 2 + 1][0]);
        d0[hb8 + 0 + tap] = r0.x;  d0[hb8 + 2 + tap] = r0.y;
        d0[hb8 + 4 + tap] = r0.z;  d0[hb8 + 6 + tap] = r0.w;
        d1[hb8 + 0 + tap] = r1.x;  d1[hb8 + 2 + tap] = r1.y;
        d1[hb8 + 4 + tap] = r1.z;  d1[hb8 + 6 + tap] = r1.w;
    }
    __syncwarp();

    // ---- z-stage: 8 pairs, float4-packed weights ----
    float z0[8], z1[8];
    #pragma unroll
    for (int pp = 0; pp < 8; pp++) { z0[pp] = sbt[lane]; z1[pp] = sbt[lane + 32]; }
    #pragma unroll 4
    for (int ip = 0; ip < 32; ip++) {
        float4 wA = sWt4[ip][lane];
        float4 wB = sWt4[ip][lane + 32];
        #pragma unroll
        for (int pp = 0; pp < 8; pp++) {
            float4 u = su4[w][pp][ip];
            z0[pp] = fmaf(wA.x, u.x, fmaf(wA.y, u.y,
                     fmaf(wA.z, u.z, fmaf(wA.w, u.w, z0[pp]))));
            z1[pp] = fmaf(wB.x, u.x, fmaf(wB.y, u.y,
                     fmaf(wB.z, u.z, fmaf(wB.w, u.w, z1[pp]))));
        }
    }
    __syncwarp();
    #pragma unroll
    for (int pp = 0; pp < 8; pp++) {
        float* zf = reinterpret_cast<float*>(&su4[w][pp][0]);
        zf[lane]      = fmaxf(z0[pp], 0.0f);
        zf[lane + 32] = fmaxf(z1[pp], 0.0f);
    }
    __syncwarp();

    // ---- y-stage: 96 outputs (8 pairs x 12) in 3 lane-rounds ----
    #pragma unroll
    for (int r = 0; r < 3; r++) {
        int q = lane + r * 32;               // 0..95
        int pp = q / PP;
        int p  = q - pp * PP;
        float y = sbo[p];
        const float4* z4 = &su4[w][pp][0];
        const float4* w4 = reinterpret_cast<const float4*>(sWoT + p * 64);
        #pragma unroll 4
        for (int oc = 0; oc < 16; oc++) {
            float4 zz = z4[oc];
            float4 ww = w4[oc];
            y = fmaf(zz.x, ww.x, fmaf(zz.y, ww.y,
                fmaf(zz.z, ww.z, fmaf(zz.w, ww.w, y))));
        }
        int node = nBase + (pp >> 1);
        int b = pp & 1;
        if (node < NN)
            out[((size_t)b * PP + p) * NN + node] = y;
    }
}

// ---------------------------------------------------------------------------
extern "C" void kernel_launch(void* const* d_in, const int* in_sizes, int n_in,
                              void* d_out, int out_size) {
    const float* x     = (const float*)d_in[0];
    const int*   row   = (const int*)  d_in[1];
    const int*   col   = (const int*)  d_in[2];
    const float* vals  = (const float*)d_in[3];
    const float* W_in  = (const float*)d_in[4];
    const float* b_in  = (const float*)d_in[5];
    const float* W_tcn = (const float*)d_in[6];
    const float* b_tcn = (const float*)d_in[7];
    const float* W_out = (const float*)d_in[8];
    const float* b_out = (const float*)d_in[9];
    float* out = (float*)d_out;

    static bool attr_set = false;
    if (!attr_set) {
        cudaFuncSetAttribute(k_final,
                             cudaFuncAttributeMaxDynamicSharedMemorySize, SM3_TOT);
        attr_set = true;
    }

    k_proj_bin<<<1250, 256>>>(x, W_in, b_in, row, col, vals);
    k_gather<<<1250, 256>>>();
    k_final<<<148, K3_THREADS, SM3_TOT>>>(W_tcn, b_tcn, W_out, b_out, out);
}

// round 12
// speedup vs baseline: 1.2993x; 1.0909x over previous
#include <cuda_runtime.h>
#include <cuda_fp16.h>
#include <cstdint>

// Problem constants
#define NB 2        // B
#define LL 16       // L
#define NN 10000    // N
#define FIN 8
#define HH 64       // H
#define PP 12       // P
#define EE 80000    // E
// Only l = 14,15 feed out[:, :, -1]. Slot s = b*2 + (l-14); row = [n][s][64].
#define SLOTS 4
#define ROWF (SLOTS * HH)   // 256 values per node row
#define CAP 64              // per-node edge bucket capacity (max deg ~35)

// Scratch: h in fp16 (512B/node row); agg never leaves registers now.
__device__ __align__(16) __half g_h16[(size_t)NN * ROWF];
__device__ int g_cnt[NN];                                // zero-init; K2 cleans
__device__ __align__(8) int2 g_edge[(size_t)NN * CAP];   // {col, val_bits}

// ---- packed fp32x2 helpers (Blackwell FFMA2; fp32-exact) ----
__device__ __forceinline__ unsigned long long fma2(unsigned long long a,
                                                   unsigned long long b,
                                                   unsigned long long c) {
    unsigned long long d;
    asm("fma.rn.f32x2 %0, %1, %2, %3;" : "=l"(d) : "l"(a), "l"(b), "l"(c));
    return d;
}
__device__ __forceinline__ unsigned long long pack2(float lo, float hi) {
    unsigned long long r;
    asm("mov.b64 %0, {%1, %2};" : "=l"(r) : "f"(lo), "f"(hi));
    return r;
}
__device__ __forceinline__ float sum2(unsigned long long v) {
    float lo, hi;
    asm("mov.b64 {%0, %1}, %2;" : "=f"(lo), "=f"(hi) : "l"(v));
    return lo + hi;
}

// ---------------------------------------------------------------------------
// K1: one warp per node: h[n,s,:] = relu(x[b,l,n,:]@W_in + b_in) -> fp16;
// edge binning AFTER proj (atomic latency becomes block tail, not a stall).
// ---------------------------------------------------------------------------
__global__ void k_proj_bin(const float* __restrict__ x,
                           const float* __restrict__ W_in,
                           const float* __restrict__ b_in,
                           const int* __restrict__ erow,
                           const int* __restrict__ ecol,
                           const float* __restrict__ evals) {
    __shared__ float sW[FIN * HH];
    __shared__ float sb[HH];
    int tid = threadIdx.x;
    int gid = blockIdx.x * blockDim.x + tid;

    for (int i = tid; i < FIN * HH; i += blockDim.x) sW[i] = W_in[i];
    if (tid < HH) sb[tid] = b_in[tid];
    __syncthreads();

    int n = blockIdx.x * 8 + (tid >> 5);   // exactly 10000
    int lane = tid & 31;
    int hh0 = lane * 2;
    int hh1 = hh0 + 1;

    #pragma unroll
    for (int s = 0; s < SLOTS; s++) {
        int b = s >> 1;
        int l = 14 + (s & 1);
        const float4* xr = reinterpret_cast<const float4*>(
            x + (((size_t)b * LL + l) * NN + n) * FIN);
        float4 x0 = __ldg(xr);       // warp-broadcast 32B row
        float4 x1 = __ldg(xr + 1);
        float xv[8] = {x0.x, x0.y, x0.z, x0.w, x1.x, x1.y, x1.z, x1.w};

        float acc0 = sb[hh0];
        float acc1 = sb[hh1];
        #pragma unroll
        for (int f = 0; f < 8; f++) {
            acc0 = fmaf(xv[f], sW[f * HH + hh0], acc0);
            acc1 = fmaf(xv[f], sW[f * HH + hh1], acc1);
        }
        __half2* hrow = reinterpret_cast<__half2*>(
            g_h16 + ((size_t)n * SLOTS + s) * HH);
        hrow[lane] = __floats2half2_rn(fmaxf(acc0, 0.0f), fmaxf(acc1, 0.0f));
    }

    // edge binning (tail work; no sync after)
    if (gid < EE) {
        int r = __ldg(erow + gid);
        int rank = atomicAdd(&g_cnt[r], 1);
        if (rank < CAP)
            g_edge[(size_t)r * CAP + rank] =
                make_int2(__ldg(ecol + gid), __float_as_int(__ldg(evals + gid)));
    }
}

// ---------------------------------------------------------------------------
// K2: fused gather + TCN-last + output projection. Persistent: grid 148 x
// 544 thr (17 warps), 1 block/SM. Each warp owns 4 nodes: gathers their agg
// in registers (fp16 h, 1 LDG.128/edge, uniform L1-hot edge records), relu ->
// su4 smem (f32x2-paired layout), z/y stages with packed fma.rn.f32x2.
// No grid barrier needed: gather and final for a node are the SAME warp.
//
// su4 float layout per (warp, pair): idx = (h>>1)*4 + tap*2 + (h&1)
//   -> 64-bit lanes: {u_t0[2ip],u_t0[2ip+1]} | {u_t1[2ip],u_t1[2ip+1]}
// sWt4 float4 [ip][o] = {w0[2ip], w0[2ip+1], w1[2ip], w1[2ip+1]}
// ---------------------------------------------------------------------------
#define K2_WARPS 17
#define K2_THREADS (K2_WARPS * 32)            // 544

#define SM_WT 0
#define SM_SU (SM_WT + 32 * 64 * 16)                      // 32768
#define SM_WO (SM_SU + K2_WARPS * 8 * 32 * 16)            // +69632 = 102400
#define SM_BT (SM_WO + PP * 64 * 4)                       // +3072  = 105472
#define SM_BO (SM_BT + 64 * 4)                            // +256   = 105728
#define SM_TOT (SM_BO + 64)                               //        = 105792

__global__ void __launch_bounds__(K2_THREADS, 1)
k_gf(const float* __restrict__ W_tcn,
     const float* __restrict__ b_tcn,
     const float* __restrict__ W_out,
     const float* __restrict__ b_out,
     float* __restrict__ out) {
    extern __shared__ char dsm[];
    float4 (*sWt4)[64] = reinterpret_cast<float4(*)[64]>(dsm + SM_WT);
    float4 (*su4)[8][32] = reinterpret_cast<float4(*)[8][32]>(dsm + SM_SU);
    float*  sWtF = reinterpret_cast<float*>(dsm + SM_WT);
    float*  sWoT = reinterpret_cast<float*>(dsm + SM_WO);
    float*  sbt  = reinterpret_cast<float*>(dsm + SM_BT);
    float*  sbo  = reinterpret_cast<float*>(dsm + SM_BO);

    int tid = threadIdx.x;
    int w = tid >> 5, lane = tid & 31;

    // ---- weight staging (coalesced reads, LDS-side transpose) ----
    // sWt4[ip][o] = W_tcn[o*192 + {6ip+0, 6ip+3, 6ip+1, 6ip+4}]
    for (int o = w; o < 64; o += K2_WARPS) {
        const float* wr = W_tcn + o * 192;
        #pragma unroll
        for (int j = 0; j < 6; j++) {
            int f = lane + 32 * j;
            float val = __ldg(wr + f);
            int ip = f / 6;
            int c  = f - ip * 6;               // 0..5
            // c: 0 -> x (w0 even), 3 -> y (w0 odd), 1 -> z (w1 even), 4 -> w
            int comp = (c == 0) ? 0 : (c == 3) ? 1 : (c == 1) ? 2 : (c == 4) ? 3 : -1;
            if (comp >= 0) sWtF[ip * 256 + o * 4 + comp] = val;
        }
    }
    for (int t = tid; t < 64 * PP; t += K2_THREADS) {
        float v = __ldg(W_out + t);
        int o = t / PP, p = t - o * PP;
        sWoT[p * 64 + o] = v;
    }
    if (tid < 64) sbt[tid] = b_tcn[tid];
    if (tid < PP) sbo[tid] = b_out[tid];
    __syncthreads();

    int wg = blockIdx.x * K2_WARPS + w;       // 0..2515
    int nBase = wg * 4;                       // 10064 >= NN
    if (nBase >= NN) return;

    // ---- gather 4 nodes; relu'd agg scattered straight into su4 ----
    const float4* hb = reinterpret_cast<const float4*>(g_h16);  // 32 f4 / row
    #pragma unroll
    for (int m = 0; m < 4; m++) {
        int node = nBase + m;
        int nd = node < NN ? node : NN - 1;
        int deg = g_cnt[nd];
        if (deg > CAP) deg = CAP;
        const int2* ep = g_edge + (size_t)nd * CAP;

        float a[8];
        #pragma unroll
        for (int i = 0; i < 8; i++) a[i] = 0.0f;

        for (int k = 0; k < deg; k += 4) {
            int   c[4];
            float v[4];
            #pragma unroll
            for (int j = 0; j < 4; j++) {
                int kk = k + j < deg ? k + j : deg - 1;
                int2 e = __ldg(ep + kk);              // uniform, L1-hot
                c[j] = e.x;
                v[j] = (k + j < deg) ? __int_as_float(e.y) : 0.0f;
            }
            float4 h4[4];
            #pragma unroll
            for (int j = 0; j < 4; j++)
                h4[j] = __ldg(hb + (size_t)c[j] * 32 + lane);
            #pragma unroll
            for (int j = 0; j < 4; j++) {
                const __half2* hp = reinterpret_cast<const __half2*>(&h4[j]);
                #pragma unroll
                for (int q = 0; q < 4; q++) {
                    float2 f = __half22float2(hp[q]);
                    a[q * 2 + 0] = fmaf(f.x, v[j], a[q * 2 + 0]);
                    a[q * 2 + 1] = fmaf(f.y, v[j], a[q * 2 + 1]);
                }
            }
        }

        // scatter relu(a) into su4: lane owns row values f = 8*lane + j
        #pragma unroll
        for (int j = 0; j < 8; j++) {
            int f = lane * 8 + j;
            int s = f >> 6;
            int h = f & 63;
            int b = s >> 1;
            int tap = s & 1;
            float* dst = reinterpret_cast<float*>(&su4[w][m * 2 + b][0]);
            dst[(h >> 1) * 4 + tap * 2 + (h & 1)] = fmaxf(a[j], 0.0f);
        }
    }
    if (lane < 4 && nBase + lane < NN) g_cnt[nBase + lane] = 0;  // self-clean
    __syncwarp();

    // ---- z-stage: 8 pairs, packed f32x2 (exact fp32) ----
    unsigned long long z0[8], z1[8];
    #pragma unroll
    for (int pp = 0; pp < 8; pp++) {
        z0[pp] = pack2(sbt[lane], 0.0f);
        z1[pp] = pack2(sbt[lane + 32], 0.0f);
    }
    #pragma unroll 4
    for (int ip = 0; ip < 32; ip++) {
        ulonglong2 wA = *reinterpret_cast<const ulonglong2*>(&sWt4[ip][lane]);
        ulonglong2 wB = *reinterpret_cast<const ulonglong2*>(&sWt4[ip][lane + 32]);
        #pragma unroll
        for (int pp = 0; pp < 8; pp++) {
            ulonglong2 u = *reinterpret_cast<const ulonglong2*>(&su4[w][pp][ip]);
            z0[pp] = fma2(u.x, wA.x, z0[pp]);   // tap0 pair
            z0[pp] = fma2(u.y, wA.y, z0[pp]);   // tap1 pair
            z1[pp] = fma2(u.x, wB.x, z1[pp]);
            z1[pp] = fma2(u.y, wB.y, z1[pp]);
        }
    }
    __syncwarp();
    #pragma unroll
    for (int pp = 0; pp < 8; pp++) {
        float* zf = reinterpret_cast<float*>(&su4[w][pp][0]);
        zf[lane]      = fmaxf(sum2(z0[pp]), 0.0f);
        zf[lane + 32] = fmaxf(sum2(z1[pp]), 0.0f);
    }
    __syncwarp();

    // ---- y-stage: 96 outputs (8 pairs x 12), packed f32x2 ----
    #pragma unroll
    for (int r = 0; r < 3; r++) {
        int q = lane + r * 32;               // 0..95
        int pp = q / PP;
        int p  = q - pp * PP;
        unsigned long long y2 = pack2(sbo[p], 0.0f);
        const ulonglong2* z4 =
            reinterpret_cast<const ulonglong2*>(&su4[w][pp][0]);
        const ulonglong2* w4 =
            reinterpret_cast<const ulonglong2*>(sWoT + p * 64);
        #pragma unroll 4
        for (int oc = 0; oc < 16; oc++) {
            ulonglong2 zz = z4[oc];
            ulonglong2 ww = w4[oc];
            y2 = fma2(zz.x, ww.x, y2);
            y2 = fma2(zz.y, ww.y, y2);
        }
        int node = nBase + (pp >> 1);
        int b = pp & 1;
        if (node < NN)
            out[((size_t)b * PP + p) * NN + node] = sum2(y2);
    }
}

// ---------------------------------------------------------------------------
extern "C" void kernel_launch(void* const* d_in, const int* in_sizes, int n_in,
                              void* d_out, int out_size) {
    const float* x     = (const float*)d_in[0];
    const int*   row   = (const int*)  d_in[1];
    const int*   col   = (const int*)  d_in[2];
    const float* vals  = (const float*)d_in[3];
    const float* W_in  = (const float*)d_in[4];
    const float* b_in  = (const float*)d_in[5];
    const float* W_tcn = (const float*)d_in[6];
    const float* b_tcn = (const float*)d_in[7];
    const float* W_out = (const float*)d_in[8];
    const float* b_out = (const float*)d_in[9];
    float* out = (float*)d_out;

    static bool attr_set = false;
    if (!attr_set) {
        cudaFuncSetAttribute(k_gf,
                             cudaFuncAttributeMaxDynamicSharedMemorySize, SM_TOT);
        attr_set = true;
    }

    k_proj_bin<<<1250, 256>>>(x, W_in, b_in, row, col, vals);
    k_gf<<<148, K2_THREADS, SM_TOT>>>(W_tcn, b_tcn, W_out, b_out, out);
}